// round 9
// baseline (speedup 1.0000x reference)
#include <cuda_runtime.h>
#include <cuda_bf16.h>

// L1OrderLoss (Chamfer-style L1, PTS_DIM=2): pred/target [8192,128] f32.
// Per row (64 2-D points): dist_1[i,c]=min_j|p[i,c]-t[j,c]|, dist_2[j,c]=min_i|.|
// out = 0.5*(sum d1 + sum d2) / (N*P*2) / 64
//
// R9: split d1/d2 into two passes so only ONE shared tile is live per loop
// (16-reg LDS batch instead of 32) -> regs ~40 -> 12 blocks/SM (75% occ).
// Inner recipe unchanged: add.rn.f32x2 on pre-negated targets + FMNMX(|src|).

#define NROWS   8192
#define PPTS    64
#define RPB     4                      // rows (warps) per block
#define THREADS (RPB * 32)             // 128
#define GRID    (NROWS / RPB)          // 2048

#define OUT_SCALE (0.5f / (8192.0f * 128.0f * 64.0f))

// Cross-launch accumulator state; last block resets -> replay-idempotent.
__device__ float        g_acc = 0.0f;
__device__ unsigned int g_cnt = 0u;

// (rx, ry) = packed f32x2 add of two b64-packed float pairs.
__device__ __forceinline__ void addx2p(unsigned long long a, unsigned long long b,
                                       float& rx, float& ry) {
    asm("{\n\t"
        ".reg .b64 rc;\n\t"
        "add.rn.f32x2 rc, %2, %3;\n\t"
        "mov.b64 {%0, %1}, rc;\n\t"
        "}"
        : "=f"(rx), "=f"(ry)
        : "l"(a), "l"(b));
}

__global__ __launch_bounds__(THREADS, 12)
void l1order_kernel(const float* __restrict__ pred,
                    const float* __restrict__ target,
                    float* __restrict__ out)
{
    __shared__ __align__(16) float2 ps[RPB][PPTS];    // pred points
    __shared__ __align__(16) float2 nts[RPB][PPTS];   // NEGATED target points
    __shared__ float warp_sums[RPB];

    const int tid = threadIdx.x;
    const int w   = tid >> 5;        // warp = local row
    const int l   = tid & 31;        // lane; owns points 2l and 2l+1
    const int row = blockIdx.x * RPB + w;

    const float4* predv4   = reinterpret_cast<const float4*>(pred);
    const float4* targetv4 = reinterpret_cast<const float4*>(target);
    float4 P = predv4[row * 32 + l];
    float4 T = targetv4[row * 32 + l];
    float4 NT = make_float4(-T.x, -T.y, -T.z, -T.w);

    reinterpret_cast<float4*>(&ps[w][0])[l]  = P;
    reinterpret_cast<float4*>(&nts[w][0])[l] = NT;

    unsigned long long pk0, pk1, ntk0, ntk1;
    asm("mov.b64 %0, {%1, %2};" : "=l"(pk0)  : "f"(P.x),  "f"(P.y));
    asm("mov.b64 %0, {%1, %2};" : "=l"(pk1)  : "f"(P.z),  "f"(P.w));
    asm("mov.b64 %0, {%1, %2};" : "=l"(ntk0) : "f"(NT.x), "f"(NT.y));
    asm("mov.b64 %0, {%1, %2};" : "=l"(ntk1) : "f"(NT.z), "f"(NT.w));

    __syncwarp();

    const ulonglong2* psv = reinterpret_cast<const ulonglong2*>(&ps[w][0]);
    const ulonglong2* ntv = reinterpret_cast<const ulonglong2*>(&nts[w][0]);

    float ax, ay;

    // ---- Pass 1: d1 (own preds vs all targets) — only nts tile live ----
    float d1x0 = 1e30f, d1y0 = 1e30f, d1x1 = 1e30f, d1y1 = 1e30f;

    #pragma unroll 4
    for (int c = 0; c < PPTS / 2; ++c) {
        ulonglong2 tt = ntv[c];   // neg targets 2c, 2c+1 (one LDS.128, broadcast)
        addx2p(pk0, tt.x, ax, ay);
        d1x0 = fminf(d1x0, fabsf(ax));  d1y0 = fminf(d1y0, fabsf(ay));
        addx2p(pk0, tt.y, ax, ay);
        d1x0 = fminf(d1x0, fabsf(ax));  d1y0 = fminf(d1y0, fabsf(ay));
        addx2p(pk1, tt.x, ax, ay);
        d1x1 = fminf(d1x1, fabsf(ax));  d1y1 = fminf(d1y1, fabsf(ay));
        addx2p(pk1, tt.y, ax, ay);
        d1x1 = fminf(d1x1, fabsf(ax));  d1y1 = fminf(d1y1, fabsf(ay));
    }

    float s = (d1x0 + d1y0) + (d1x1 + d1y1);   // collapse -> frees accumulators

    // ---- Pass 2: d2 (all preds vs own targets) — only ps tile live ----
    float d2x0 = 1e30f, d2y0 = 1e30f, d2x1 = 1e30f, d2y1 = 1e30f;

    #pragma unroll 4
    for (int c = 0; c < PPTS / 2; ++c) {
        ulonglong2 pp = psv[c];   // preds 2c, 2c+1 (one LDS.128, broadcast)
        addx2p(pp.x, ntk0, ax, ay);
        d2x0 = fminf(d2x0, fabsf(ax));  d2y0 = fminf(d2y0, fabsf(ay));
        addx2p(pp.y, ntk0, ax, ay);
        d2x0 = fminf(d2x0, fabsf(ax));  d2y0 = fminf(d2y0, fabsf(ay));
        addx2p(pp.x, ntk1, ax, ay);
        d2x1 = fminf(d2x1, fabsf(ax));  d2y1 = fminf(d2y1, fabsf(ay));
        addx2p(pp.y, ntk1, ax, ay);
        d2x1 = fminf(d2x1, fabsf(ax));  d2y1 = fminf(d2y1, fabsf(ay));
    }

    s += (d2x0 + d2y0) + (d2x1 + d2y1);

    #pragma unroll
    for (int off = 16; off > 0; off >>= 1)
        s += __shfl_down_sync(0xFFFFFFFFu, s, off);

    if (l == 0) warp_sums[w] = s;
    __syncthreads();

    if (tid == 0) {
        float v = (warp_sums[0] + warp_sums[1]) + (warp_sums[2] + warp_sums[3]);
        atomicAdd(&g_acc, v);
        __threadfence();
        unsigned int done = atomicAdd(&g_cnt, 1u);
        if (done == GRID - 1u) {
            out[0] = g_acc * OUT_SCALE;   // all g_acc adds visible (fence-before-count)
            g_acc = 0.0f;
            __threadfence();
            g_cnt = 0u;
        }
    }
}

extern "C" void kernel_launch(void* const* d_in, const int* in_sizes, int n_in,
                              void* d_out, int out_size)
{
    const float* pred   = (const float*)d_in[0];
    const float* target = (const float*)d_in[1];
    float* out = (float*)d_out;

    l1order_kernel<<<GRID, THREADS>>>(pred, target, out);
}

// round 10
// speedup vs baseline: 1.0173x; 1.0173x over previous
#include <cuda_runtime.h>
#include <cuda_bf16.h>

// L1OrderLoss (Chamfer-style L1, PTS_DIM=2): pred/target [8192,128] f32.
// Per row (64 2-D points): dist_1[i,c]=min_j|p[i,c]-t[j,c]|, dist_2[j,c]=min_i|.|
// out = 0.5*(sum d1 + sum d2) / (N*P*2) / 64
//
// R10 = R5 body VERBATIM (best measured kernel: 11.4us; unroll-4,
// front-batched LDS.128, packed add.rn.f32x2 + scalar FMNMX(|src|),
// launch_bounds(128,8)) + fused finalize (single graph node, saves ~1.8us
// of per-launch overhead; verified bit-exact in R9).

#define NROWS   8192
#define PPTS    64
#define RPB     4                      // rows (warps) per block
#define THREADS (RPB * 32)             // 128
#define GRID    (NROWS / RPB)          // 2048

#define OUT_SCALE (0.5f / (8192.0f * 128.0f * 64.0f))

// Cross-launch accumulator state; last block resets -> replay-idempotent.
__device__ float        g_acc = 0.0f;
__device__ unsigned int g_cnt = 0u;

// (rx, ry) = packed f32x2 add of two b64-packed float pairs.
__device__ __forceinline__ void addx2p(unsigned long long a, unsigned long long b,
                                       float& rx, float& ry) {
    asm("{\n\t"
        ".reg .b64 rc;\n\t"
        "add.rn.f32x2 rc, %2, %3;\n\t"
        "mov.b64 {%0, %1}, rc;\n\t"
        "}"
        : "=f"(rx), "=f"(ry)
        : "l"(a), "l"(b));
}

__global__ __launch_bounds__(THREADS, 8)
void l1order_kernel(const float* __restrict__ pred,
                    const float* __restrict__ target,
                    float* __restrict__ out)
{
    __shared__ __align__(16) float2 ps[RPB][PPTS];    // pred points
    __shared__ __align__(16) float2 nts[RPB][PPTS];   // NEGATED target points
    __shared__ float warp_sums[RPB];

    const int tid = threadIdx.x;
    const int w   = tid >> 5;        // warp = local row
    const int l   = tid & 31;        // lane; owns points 2l and 2l+1
    const int row = blockIdx.x * RPB + w;

    const float4* predv4   = reinterpret_cast<const float4*>(pred);
    const float4* targetv4 = reinterpret_cast<const float4*>(target);
    float4 P = predv4[row * 32 + l];
    float4 T = targetv4[row * 32 + l];
    float4 NT = make_float4(-T.x, -T.y, -T.z, -T.w);

    reinterpret_cast<float4*>(&ps[w][0])[l]  = P;
    reinterpret_cast<float4*>(&nts[w][0])[l] = NT;

    unsigned long long pk0, pk1, ntk0, ntk1;
    asm("mov.b64 %0, {%1, %2};" : "=l"(pk0)  : "f"(P.x),  "f"(P.y));
    asm("mov.b64 %0, {%1, %2};" : "=l"(pk1)  : "f"(P.z),  "f"(P.w));
    asm("mov.b64 %0, {%1, %2};" : "=l"(ntk0) : "f"(NT.x), "f"(NT.y));
    asm("mov.b64 %0, {%1, %2};" : "=l"(ntk1) : "f"(NT.z), "f"(NT.w));

    __syncwarp();

    // 8 independent min chains.
    float d1x0 = 1e30f, d1y0 = 1e30f, d1x1 = 1e30f, d1y1 = 1e30f;
    float d2x0 = 1e30f, d2y0 = 1e30f, d2x1 = 1e30f, d2y1 = 1e30f;

    const ulonglong2* psv = reinterpret_cast<const ulonglong2*>(&ps[w][0]);
    const ulonglong2* ntv = reinterpret_cast<const ulonglong2*>(&nts[w][0]);

    #pragma unroll 4
    for (int c = 0; c < PPTS / 2; ++c) {
        ulonglong2 tt = ntv[c];   // neg targets 2c, 2c+1 (one LDS.128, broadcast)
        ulonglong2 pp = psv[c];   // preds       2c, 2c+1 (one LDS.128, broadcast)

        float ax, ay;
        // d1 side: own preds vs targets 2c, 2c+1
        addx2p(pk0, tt.x, ax, ay);
        d1x0 = fminf(d1x0, fabsf(ax));  d1y0 = fminf(d1y0, fabsf(ay));
        addx2p(pk0, tt.y, ax, ay);
        d1x0 = fminf(d1x0, fabsf(ax));  d1y0 = fminf(d1y0, fabsf(ay));
        addx2p(pk1, tt.x, ax, ay);
        d1x1 = fminf(d1x1, fabsf(ax));  d1y1 = fminf(d1y1, fabsf(ay));
        addx2p(pk1, tt.y, ax, ay);
        d1x1 = fminf(d1x1, fabsf(ax));  d1y1 = fminf(d1y1, fabsf(ay));

        // d2 side: preds 2c, 2c+1 vs own targets
        addx2p(pp.x, ntk0, ax, ay);
        d2x0 = fminf(d2x0, fabsf(ax));  d2y0 = fminf(d2y0, fabsf(ay));
        addx2p(pp.y, ntk0, ax, ay);
        d2x0 = fminf(d2x0, fabsf(ax));  d2y0 = fminf(d2y0, fabsf(ay));
        addx2p(pp.x, ntk1, ax, ay);
        d2x1 = fminf(d2x1, fabsf(ax));  d2y1 = fminf(d2y1, fabsf(ay));
        addx2p(pp.y, ntk1, ax, ay);
        d2x1 = fminf(d2x1, fabsf(ax));  d2y1 = fminf(d2y1, fabsf(ay));
    }

    float s = ((d1x0 + d1y0) + (d1x1 + d1y1))
            + ((d2x0 + d2y0) + (d2x1 + d2y1));

    #pragma unroll
    for (int off = 16; off > 0; off >>= 1)
        s += __shfl_down_sync(0xFFFFFFFFu, s, off);

    if (l == 0) warp_sums[w] = s;
    __syncthreads();

    if (tid == 0) {
        float v = (warp_sums[0] + warp_sums[1]) + (warp_sums[2] + warp_sums[3]);
        atomicAdd(&g_acc, v);
        __threadfence();
        unsigned int done = atomicAdd(&g_cnt, 1u);
        if (done == GRID - 1u) {
            out[0] = g_acc * OUT_SCALE;   // all g_acc adds visible (fence-before-count)
            g_acc = 0.0f;
            __threadfence();
            g_cnt = 0u;
        }
    }
}

extern "C" void kernel_launch(void* const* d_in, const int* in_sizes, int n_in,
                              void* d_out, int out_size)
{
    const float* pred   = (const float*)d_in[0];
    const float* target = (const float*)d_in[1];
    float* out = (float*)d_out;

    l1order_kernel<<<GRID, THREADS>>>(pred, target, out);
}